// round 4
// baseline (speedup 1.0000x reference)
#include <cuda_runtime.h>

// x: (4096, 32, 500) f32, W: (1,32) f32, b: (1,) f32 -> out: (4096,) f32
// out[s] = mean_a | sum_c W[c]*x[s][c][a] + b | + 0.01

#define N_SAMPLES 4096
#define N_CH      32
#define N_ASSETS  500
#define VEC4_PER_ROW 125          // 500 / 4
#define THREADS   128
#define S_PER_CTA 2

__global__ __launch_bounds__(THREADS)
void gamma_kernel(const float* __restrict__ x,
                  const float* __restrict__ W,
                  const float* __restrict__ b,
                  float* __restrict__ out)
{
    const int s0  = blockIdx.x * S_PER_CTA;
    const int tid = threadIdx.x;

    const float bv = __ldg(b);

    const float4* xs0 = reinterpret_cast<const float4*>(x + (size_t)s0 * (N_CH * N_ASSETS));
    const float4* xs1 = reinterpret_cast<const float4*>(x + (size_t)(s0 + 1) * (N_CH * N_ASSETS));

    float4 acc0 = make_float4(0.f, 0.f, 0.f, 0.f);
    float4 acc1 = make_float4(0.f, 0.f, 0.f, 0.f);

    if (tid < VEC4_PER_ROW) {
        #pragma unroll
        for (int c = 0; c < N_CH; ++c) {
            const float wc = __ldg(&W[c]);
            const int off = c * VEC4_PER_ROW + tid;
            // two independent streaming (evict-first) loads per iteration
            float4 v0 = __ldcs(&xs0[off]);
            float4 v1 = __ldcs(&xs1[off]);
            acc0.x = fmaf(wc, v0.x, acc0.x);
            acc0.y = fmaf(wc, v0.y, acc0.y);
            acc0.z = fmaf(wc, v0.z, acc0.z);
            acc0.w = fmaf(wc, v0.w, acc0.w);
            acc1.x = fmaf(wc, v1.x, acc1.x);
            acc1.y = fmaf(wc, v1.y, acc1.y);
            acc1.z = fmaf(wc, v1.z, acc1.z);
            acc1.w = fmaf(wc, v1.w, acc1.w);
        }
    }

    float p0 = 0.f, p1 = 0.f;
    if (tid < VEC4_PER_ROW) {
        p0 = fabsf(acc0.x + bv) + fabsf(acc0.y + bv)
           + fabsf(acc0.z + bv) + fabsf(acc0.w + bv);
        p1 = fabsf(acc1.x + bv) + fabsf(acc1.y + bv)
           + fabsf(acc1.z + bv) + fabsf(acc1.w + bv);
    }

    // warp reduce both partials
    #pragma unroll
    for (int off = 16; off > 0; off >>= 1) {
        p0 += __shfl_xor_sync(0xFFFFFFFFu, p0, off);
        p1 += __shfl_xor_sync(0xFFFFFFFFu, p1, off);
    }

    __shared__ float warp_sums0[THREADS / 32];
    __shared__ float warp_sums1[THREADS / 32];
    const int wid = tid >> 5;
    const int lid = tid & 31;
    if (lid == 0) { warp_sums0[wid] = p0; warp_sums1[wid] = p1; }
    __syncthreads();

    if (tid == 0) {
        float t0 = warp_sums0[0] + warp_sums0[1] + warp_sums0[2] + warp_sums0[3];
        out[s0] = t0 * (1.0f / (float)N_ASSETS) + 0.01f;
    } else if (tid == 32) {
        float t1 = warp_sums1[0] + warp_sums1[1] + warp_sums1[2] + warp_sums1[3];
        out[s0 + 1] = t1 * (1.0f / (float)N_ASSETS) + 0.01f;
    }
}

extern "C" void kernel_launch(void* const* d_in, const int* in_sizes, int n_in,
                              void* d_out, int out_size)
{
    const float* x = (const float*)d_in[0];
    const float* W = (const float*)d_in[1];
    const float* b = (const float*)d_in[2];
    float* out = (float*)d_out;
    (void)in_sizes; (void)n_in; (void)out_size;

    gamma_kernel<<<N_SAMPLES / S_PER_CTA, THREADS>>>(x, W, b, out);
}

// round 6
// speedup vs baseline: 1.1977x; 1.1977x over previous
#include <cuda_runtime.h>

// x: (4096, 32, 500) f32, W: (1,32) f32, b: (1,) f32 -> out: (4096,) f32
// out[s] = mean_a | sum_c W[c]*x[s][c][a] + b | + 0.01

#define N_SAMPLES 4096
#define N_CH      32
#define N_ASSETS  500
#define VEC4_PER_ROW 125          // 500 / 4
#define THREADS   128

__global__ __launch_bounds__(THREADS)
void gamma_kernel(const float* __restrict__ x,
                  const float* __restrict__ W,
                  const float* __restrict__ b,
                  float* __restrict__ out)
{
    const int s   = blockIdx.x;
    const int tid = threadIdx.x;

    // Stage W (and b) in shared memory once: removes the per-iteration
    // W LDG from the mainloop (halves LDG issue count).
    __shared__ float ws[N_CH];
    __shared__ float bs;
    if (tid < N_CH) ws[tid] = W[tid];
    if (tid == N_CH) bs = b[0];
    __syncthreads();

    const float* xs = x + (size_t)s * (N_CH * N_ASSETS);

    float4 acc = make_float4(0.f, 0.f, 0.f, 0.f);

    if (tid < VEC4_PER_ROW) {
        const float4* base = reinterpret_cast<const float4*>(xs) + tid;
        #pragma unroll
        for (int c = 0; c < N_CH; ++c) {
            const float wc = ws[c];
            float4 v = base[c * VEC4_PER_ROW];
            acc.x = fmaf(wc, v.x, acc.x);
            acc.y = fmaf(wc, v.y, acc.y);
            acc.z = fmaf(wc, v.z, acc.z);
            acc.w = fmaf(wc, v.w, acc.w);
        }
    }

    const float bv = bs;
    float part = 0.f;
    if (tid < VEC4_PER_ROW) {
        part = fabsf(acc.x + bv) + fabsf(acc.y + bv)
             + fabsf(acc.z + bv) + fabsf(acc.w + bv);
    }

    // warp reduce
    #pragma unroll
    for (int off = 16; off > 0; off >>= 1)
        part += __shfl_xor_sync(0xFFFFFFFFu, part, off);

    __shared__ float warp_sums[THREADS / 32];
    const int wid = tid >> 5;
    const int lid = tid & 31;
    if (lid == 0) warp_sums[wid] = part;
    __syncthreads();

    if (tid == 0) {
        float total = warp_sums[0] + warp_sums[1] + warp_sums[2] + warp_sums[3];
        out[s] = total * (1.0f / (float)N_ASSETS) + 0.01f;
    }
}

extern "C" void kernel_launch(void* const* d_in, const int* in_sizes, int n_in,
                              void* d_out, int out_size)
{
    const float* x = (const float*)d_in[0];
    const float* W = (const float*)d_in[1];
    const float* b = (const float*)d_in[2];
    float* out = (float*)d_out;
    (void)in_sizes; (void)n_in; (void)out_size;

    gamma_kernel<<<N_SAMPLES, THREADS>>>(x, W, b, out);
}